// round 7
// baseline (speedup 1.0000x reference)
#include <cuda_runtime.h>
#include <cstdint>

#define TT 100
#define BB 1024
#define NIN 784
#define NHID 1000
#define NOUT 10

// Eigen gebp k-blocking (validated R5): kc = 320
#define KC 320

// cur1 scratch [T, B, NHID] = 409.6 MB
__device__ float g_cur1[(size_t)TT * BB * NHID];

// ---------------------------------------------------------------------------
// Kernel A (unchanged from R6 -- at FFMA issue roofline):
// cur1[m,n] = ((P0+P1)+P2) + b1[n], P_i = fma chain over k-panel i (kc=320).
// ---------------------------------------------------------------------------
#define BM 128
#define BN 128
#define BK 8
#define PADR 132
#define NITER (NIN / BK)      // 98

__global__ void __launch_bounds__(256, 1) gemm_cur1_kernel(
    const float* __restrict__ X,   // [M=T*B, K]
    const float* __restrict__ W1,  // [NHID, K]
    const float* __restrict__ b1)  // [NHID]
{
    __shared__ float As[2][BK][PADR];
    __shared__ float Bs[2][BK][PADR];

    const int tid = threadIdx.x;
    const int tx = tid & 15;
    const int ty = tid >> 4;
    const int m0 = blockIdx.y * BM;
    const int n0 = blockIdx.x * BN;

    const int lrow = tid >> 1;
    const int lcol = (tid & 1) * 4;

    const float* Aptr = X  + (size_t)(m0 + lrow) * NIN + lcol;
    const float* Bptr = W1 + (size_t)(n0 + lrow) * NIN + lcol;
    const bool bvalid = (n0 + lrow) < NHID;

    float c[8][8];
#pragma unroll
    for (int i = 0; i < 8; ++i)
#pragma unroll
        for (int j = 0; j < 8; ++j) c[i][j] = 0.f;

    float pa[8][8];

    {
        float4 av = *(const float4*)(Aptr);
        float4 bv = bvalid ? *(const float4*)(Bptr) : make_float4(0, 0, 0, 0);
        As[0][lcol + 0][lrow] = av.x;
        As[0][lcol + 1][lrow] = av.y;
        As[0][lcol + 2][lrow] = av.z;
        As[0][lcol + 3][lrow] = av.w;
        Bs[0][lcol + 0][lrow] = bv.x;
        Bs[0][lcol + 1][lrow] = bv.y;
        Bs[0][lcol + 2][lrow] = bv.z;
        Bs[0][lcol + 3][lrow] = bv.w;
    }
    __syncthreads();

    int buf = 0;
#pragma unroll 1
    for (int it = 0; it < NITER; ++it) {
        if (it == 0 || it == 40 || it == 80) {
#pragma unroll
            for (int i = 0; i < 8; ++i)
#pragma unroll
                for (int j = 0; j < 8; ++j) pa[i][j] = 0.f;
        }

        const bool notlast = (it < NITER - 1);
        float4 nav = make_float4(0, 0, 0, 0), nbv = make_float4(0, 0, 0, 0);
        if (notlast) {
            nav = *(const float4*)(Aptr + (it + 1) * BK);
            if (bvalid) nbv = *(const float4*)(Bptr + (it + 1) * BK);
        }

#pragma unroll
        for (int k = 0; k < BK; ++k) {
            float a[8], b[8];
            *(float4*)(a)     = *(const float4*)(&As[buf][k][ty * 8]);
            *(float4*)(a + 4) = *(const float4*)(&As[buf][k][ty * 8 + 4]);
            *(float4*)(b)     = *(const float4*)(&Bs[buf][k][tx * 8]);
            *(float4*)(b + 4) = *(const float4*)(&Bs[buf][k][tx * 8 + 4]);
#pragma unroll
            for (int i = 0; i < 8; ++i)
#pragma unroll
                for (int j = 0; j < 8; ++j)
                    pa[i][j] = __fmaf_rn(a[i], b[j], pa[i][j]);
        }

        if (it == 39 || it == 79 || it == NITER - 1) {
#pragma unroll
            for (int i = 0; i < 8; ++i)
#pragma unroll
                for (int j = 0; j < 8; ++j) c[i][j] = __fadd_rn(c[i][j], pa[i][j]);
        }

        if (notlast) {
            const int nb = buf ^ 1;
            As[nb][lcol + 0][lrow] = nav.x;
            As[nb][lcol + 1][lrow] = nav.y;
            As[nb][lcol + 2][lrow] = nav.z;
            As[nb][lcol + 3][lrow] = nav.w;
            Bs[nb][lcol + 0][lrow] = nbv.x;
            Bs[nb][lcol + 1][lrow] = nbv.y;
            Bs[nb][lcol + 2][lrow] = nbv.z;
            Bs[nb][lcol + 3][lrow] = nbv.w;
            __syncthreads();
            buf = nb;
        }
    }

#pragma unroll
    for (int i = 0; i < 8; ++i) {
        const size_t row = (size_t)(m0 + ty * 8 + i) * NHID;
#pragma unroll
        for (int j = 0; j < 8; ++j) {
            const int n = n0 + tx * 8 + j;
            if (n < NHID) g_cur1[row + n] = __fadd_rn(c[i][j], b1[n]);
        }
    }
}

// ---------------------------------------------------------------------------
// Kernel B v2: 128 threads, 8 units/thread (h = 128*i + tid).
// Ballot word j = 4i+warp covers h in [32j, 32j+32) -- ascending.
// Per step: ballots -> ONE __syncthreads -> warp 0 builds a compact ascending
// spike-index list (popc+scan, panel splits at words 10/20 = h 320/640) and
// lanes 0..9 run the layer-2 chain over the list (fadd-chain, loads
// pipelined). Parity double buffers let warps 1-3 run one step ahead.
// Bitwise identical to the dense kc=320 chain: fmaf(0,w,acc)==acc and
// pacc is never -0 (sum of adds starting from +0).
// ---------------------------------------------------------------------------
#define W2P 1001   // padded stride: 1001 % 32 = 9 -> 10 dot lanes hit 10 banks

__global__ void __launch_bounds__(128) lif_kernel(
    const float* __restrict__ W2,   // [NOUT, NHID]
    const float* __restrict__ b2,   // [NOUT]
    float* __restrict__ out)
{
    const int b    = blockIdx.x;
    const int tid  = threadIdx.x;
    const int warp = tid >> 5, lane = tid & 31;

    __shared__ float    W2s[NOUT * W2P];    // ~40.0 KB
    __shared__ uint32_t masks[2][32];
    __shared__ uint16_t list[2][1024];      // 4 KB

    for (int i = tid; i < NOUT * NHID; i += 128) {
        const int o = i / NHID, h = i - o * NHID;
        W2s[o * W2P + h] = W2[i];
    }

    float mem1[8];
#pragma unroll
    for (int i = 0; i < 8; ++i) mem1[i] = 0.f;
    uint32_t rstb = 0;

    float mem2 = 0.f, rst2 = 0.f, b2v = 0.f;
    if (tid < NOUT) b2v = b2[tid];

    const float* cr0 = g_cur1 + (size_t)b * NHID;
    const size_t tstride = (size_t)BB * NHID;

    float cv[8];
#pragma unroll
    for (int i = 0; i < 8; ++i) {
        const int h = i * 128 + tid;
        cv[i] = (h < NHID) ? __ldg(cr0 + h) : 0.f;
    }
    __syncthreads();

    int par = 0;
    for (int t = 0; t < TT; ++t) {
        // layer-1 update + ballots
        uint32_t nrst = 0;
#pragma unroll
        for (int i = 0; i < 8; ++i) {
            const int h = i * 128 + tid;
            const float rstv = ((rstb >> i) & 1u) ? 1.f : 0.f;
            const float m = __fsub_rn(__fadd_rn(__fmul_rn(0.9f, mem1[i]), cv[i]), rstv);
            mem1[i] = m;
            const bool s = (m > 1.0f) && (h < NHID);
            const uint32_t bal = __ballot_sync(0xffffffffu, s);
            if (lane == 0) masks[par][i * 4 + warp] = bal;
            if (s) nrst |= (1u << i);
        }
        rstb = nrst;

        // prefetch next step's currents
        float nvv[8];
#pragma unroll
        for (int i = 0; i < 8; ++i) nvv[i] = 0.f;
        if (t + 1 < TT) {
            const float* crn = cr0 + (size_t)(t + 1) * tstride;
#pragma unroll
            for (int i = 0; i < 8; ++i) {
                const int h = i * 128 + tid;
                if (h < NHID) nvv[i] = __ldg(crn + h);
            }
        }
        __syncthreads();   // the ONLY block-wide sync per step

        if (warp == 0) {
            // build compact ascending spike list
            const uint32_t mw = masks[par][lane];
            const int cnt = __popc(mw);
            int inc = cnt;
#pragma unroll
            for (int d = 1; d < 32; d <<= 1) {
                const int v = __shfl_up_sync(0xffffffffu, inc, d);
                if (lane >= d) inc += v;
            }
            const int excl = inc - cnt;
            const int tot = __shfl_sync(0xffffffffu, inc, 31);
            const int p1  = __shfl_sync(0xffffffffu, excl, 10);  // h = 320
            const int p2  = __shfl_sync(0xffffffffu, excl, 20);  // h = 640
            {
                uint32_t m2w = mw;
                int o = excl;
                const int base = lane * 32;
                while (m2w) {
                    const int bi = __ffs(m2w) - 1;
                    list[par][o++] = (uint16_t)(base + bi);
                    m2w &= m2w - 1;
                }
            }
            __syncwarp();

            if (lane < NOUT) {
                const float* wrow = &W2s[lane * W2P];
                const uint16_t* L = list[par];
                float acc = 0.f;
                int s0 = 0, s1 = p1;
#pragma unroll
                for (int seg = 0; seg < 3; ++seg) {
                    float pacc = 0.f;
#pragma unroll 8
                    for (int ii = s0; ii < s1; ++ii)
                        pacc = __fadd_rn(pacc, wrow[L[ii]]);
                    acc = __fadd_rn(acc, pacc);
                    s0 = s1;
                    s1 = (seg == 0) ? p2 : tot;
                }
                const float c2 = __fadd_rn(acc, b2v);
                const float m2 = __fsub_rn(__fadd_rn(__fmul_rn(0.9f, mem2), c2), rst2);
                const float s2 = (m2 > 1.0f) ? 1.0f : 0.0f;
                mem2 = m2;
                rst2 = s2;
                const size_t idx = ((size_t)t * BB + b) * NOUT + lane;
                out[idx] = s2;
                out[(size_t)TT * BB * NOUT + idx] = m2;
            }
        }

        par ^= 1;
#pragma unroll
        for (int i = 0; i < 8; ++i) cv[i] = nvv[i];
    }
}

// ---------------------------------------------------------------------------
extern "C" void kernel_launch(void* const* d_in, const int* in_sizes, int n_in,
                              void* d_out, int out_size)
{
    const float* x  = (const float*)d_in[0];
    const float* W1 = (const float*)d_in[1];
    const float* b1 = (const float*)d_in[2];
    const float* W2 = (const float*)d_in[3];
    const float* b2 = (const float*)d_in[4];
    float* out = (float*)d_out;

    dim3 grid((NHID + BN - 1) / BN, (TT * BB) / BM);   // (8, 800)
    gemm_cur1_kernel<<<grid, 256>>>(x, W1, b1);

    lif_kernel<<<BB, 128>>>(W2, b2, out);
}

// round 8
// speedup vs baseline: 1.5670x; 1.5670x over previous
#include <cuda_runtime.h>
#include <cstdint>

#define TT 100
#define BB 1024
#define NIN 784
#define NHID 1000
#define NOUT 10

// Eigen gebp k-blocking (validated R5): kc = 320
#define KC 320

// cur1 scratch [T, B, NHID] = 409.6 MB
__device__ float g_cur1[(size_t)TT * BB * NHID];

typedef unsigned long long u64;

__device__ __forceinline__ u64 pack2(float x, float y) {
    u64 r;
    asm("mov.b64 %0, {%1,%2};" : "=l"(r) : "f"(x), "f"(y));
    return r;
}
__device__ __forceinline__ u64 fma2(u64 a, u64 b, u64 c) {
    u64 d;
    asm("fma.rn.f32x2 %0, %1, %2, %3;" : "=l"(d) : "l"(a), "l"(b), "l"(c));
    return d;
}
__device__ __forceinline__ u64 add2(u64 a, u64 b) {
    u64 d;
    asm("add.rn.f32x2 %0, %1, %2;" : "=l"(d) : "l"(a), "l"(b));
    return d;
}
__device__ __forceinline__ void unpack2(u64 v, float& x, float& y) {
    asm("mov.b64 {%0,%1}, %2;" : "=f"(x), "=f"(y) : "l"(v));
}

// ---------------------------------------------------------------------------
// Kernel A: cur1[m,n] = ((P0+P1)+P2) + b1[n], P_i = fma chain over k-panel i
// (kc=320). Packed FFMA2 (fma.rn.f32x2): each lane is an independent RN fp32
// fma -> bitwise identical to the scalar chain. 128x128 tile, 8x8 microtile,
// double-buffered smem, register prefetch, one sync per k-step.
// ---------------------------------------------------------------------------
#define BM 128
#define BN 128
#define BK 8
#define PADR 132              // row stride (floats); 528B rows keep 8B align
#define NITER (NIN / BK)      // 98

__global__ void __launch_bounds__(256, 1) gemm_cur1_kernel(
    const float* __restrict__ X,   // [M=T*B, K]
    const float* __restrict__ W1,  // [NHID, K]
    const float* __restrict__ b1)  // [NHID]
{
    __shared__ float As[2][BK][PADR];
    __shared__ float Bs[2][BK][PADR];

    const int tid = threadIdx.x;
    const int tx = tid & 15;
    const int ty = tid >> 4;
    const int m0 = blockIdx.y * BM;
    const int n0 = blockIdx.x * BN;

    const int lrow = tid >> 1;
    const int lcol = (tid & 1) * 4;

    const float* Aptr = X  + (size_t)(m0 + lrow) * NIN + lcol;
    const float* Bptr = W1 + (size_t)(n0 + lrow) * NIN + lcol;
    const bool bvalid = (n0 + lrow) < NHID;

    u64 c2[8][4];     // committed accumulators, packed pairs along n
#pragma unroll
    for (int i = 0; i < 8; ++i)
#pragma unroll
        for (int j = 0; j < 4; ++j) c2[i][j] = 0ull;

    u64 pa2[8][4];    // panel accumulators

    {
        float4 av = *(const float4*)(Aptr);
        float4 bv = bvalid ? *(const float4*)(Bptr) : make_float4(0, 0, 0, 0);
        As[0][lcol + 0][lrow] = av.x;
        As[0][lcol + 1][lrow] = av.y;
        As[0][lcol + 2][lrow] = av.z;
        As[0][lcol + 3][lrow] = av.w;
        Bs[0][lcol + 0][lrow] = bv.x;
        Bs[0][lcol + 1][lrow] = bv.y;
        Bs[0][lcol + 2][lrow] = bv.z;
        Bs[0][lcol + 3][lrow] = bv.w;
    }
    __syncthreads();

    int buf = 0;
#pragma unroll 1
    for (int it = 0; it < NITER; ++it) {
        if (it == 0 || it == 40 || it == 80) {
#pragma unroll
            for (int i = 0; i < 8; ++i)
#pragma unroll
                for (int j = 0; j < 4; ++j) pa2[i][j] = 0ull;
        }

        const bool notlast = (it < NITER - 1);
        float4 nav = make_float4(0, 0, 0, 0), nbv = make_float4(0, 0, 0, 0);
        if (notlast) {
            nav = *(const float4*)(Aptr + (it + 1) * BK);
            if (bvalid) nbv = *(const float4*)(Bptr + (it + 1) * BK);
        }

#pragma unroll
        for (int k = 0; k < BK; ++k) {
            float a[8];
            *(float4*)(a)     = *(const float4*)(&As[buf][k][ty * 8]);
            *(float4*)(a + 4) = *(const float4*)(&As[buf][k][ty * 8 + 4]);
            u64 b2[4];
#pragma unroll
            for (int j = 0; j < 4; ++j)
                b2[j] = *(const u64*)(&Bs[buf][k][tx * 8 + 2 * j]);
#pragma unroll
            for (int i = 0; i < 8; ++i) {
                const u64 a2 = pack2(a[i], a[i]);
#pragma unroll
                for (int j = 0; j < 4; ++j)
                    pa2[i][j] = fma2(a2, b2[j], pa2[i][j]);
            }
        }

        // Eigen commit: C += panel, lanewise RN adds (== scalar __fadd_rn)
        if (it == 39 || it == 79 || it == NITER - 1) {
#pragma unroll
            for (int i = 0; i < 8; ++i)
#pragma unroll
                for (int j = 0; j < 4; ++j) c2[i][j] = add2(c2[i][j], pa2[i][j]);
        }

        if (notlast) {
            const int nb = buf ^ 1;
            As[nb][lcol + 0][lrow] = nav.x;
            As[nb][lcol + 1][lrow] = nav.y;
            As[nb][lcol + 2][lrow] = nav.z;
            As[nb][lcol + 3][lrow] = nav.w;
            Bs[nb][lcol + 0][lrow] = nbv.x;
            Bs[nb][lcol + 1][lrow] = nbv.y;
            Bs[nb][lcol + 2][lrow] = nbv.z;
            Bs[nb][lcol + 3][lrow] = nbv.w;
            __syncthreads();
            buf = nb;
        }
    }

#pragma unroll
    for (int i = 0; i < 8; ++i) {
        const size_t row = (size_t)(m0 + ty * 8 + i) * NHID;
#pragma unroll
        for (int j = 0; j < 4; ++j) {
            float lo, hi;
            unpack2(c2[i][j], lo, hi);
            const int n = n0 + tx * 8 + 2 * j;
            if (n < NHID)     g_cur1[row + n]     = __fadd_rn(lo, b1[n]);
            if (n + 1 < NHID) g_cur1[row + n + 1] = __fadd_rn(hi, b1[n + 1]);
        }
    }
}

// ---------------------------------------------------------------------------
// Kernel B (R7 version, 570us, bitwise-validated): 128 threads, 8 units/thr,
// ballot masks -> compact ascending spike list -> sparse fadd chain with
// kc=320 panel breaks. One block-wide sync per step, parity double buffers.
// ---------------------------------------------------------------------------
#define W2P 1001

__global__ void __launch_bounds__(128) lif_kernel(
    const float* __restrict__ W2,   // [NOUT, NHID]
    const float* __restrict__ b2,   // [NOUT]
    float* __restrict__ out)
{
    const int b    = blockIdx.x;
    const int tid  = threadIdx.x;
    const int warp = tid >> 5, lane = tid & 31;

    __shared__ float    W2s[NOUT * W2P];
    __shared__ uint32_t masks[2][32];
    __shared__ uint16_t list[2][1024];

    for (int i = tid; i < NOUT * NHID; i += 128) {
        const int o = i / NHID, h = i - o * NHID;
        W2s[o * W2P + h] = W2[i];
    }

    float mem1[8];
#pragma unroll
    for (int i = 0; i < 8; ++i) mem1[i] = 0.f;
    uint32_t rstb = 0;

    float mem2 = 0.f, rst2 = 0.f, b2v = 0.f;
    if (tid < NOUT) b2v = b2[tid];

    const float* cr0 = g_cur1 + (size_t)b * NHID;
    const size_t tstride = (size_t)BB * NHID;

    float cv[8];
#pragma unroll
    for (int i = 0; i < 8; ++i) {
        const int h = i * 128 + tid;
        cv[i] = (h < NHID) ? __ldg(cr0 + h) : 0.f;
    }
    __syncthreads();

    int par = 0;
    for (int t = 0; t < TT; ++t) {
        uint32_t nrst = 0;
#pragma unroll
        for (int i = 0; i < 8; ++i) {
            const int h = i * 128 + tid;
            const float rstv = ((rstb >> i) & 1u) ? 1.f : 0.f;
            const float m = __fsub_rn(__fadd_rn(__fmul_rn(0.9f, mem1[i]), cv[i]), rstv);
            mem1[i] = m;
            const bool s = (m > 1.0f) && (h < NHID);
            const uint32_t bal = __ballot_sync(0xffffffffu, s);
            if (lane == 0) masks[par][i * 4 + warp] = bal;
            if (s) nrst |= (1u << i);
        }
        rstb = nrst;

        float nvv[8];
#pragma unroll
        for (int i = 0; i < 8; ++i) nvv[i] = 0.f;
        if (t + 1 < TT) {
            const float* crn = cr0 + (size_t)(t + 1) * tstride;
#pragma unroll
            for (int i = 0; i < 8; ++i) {
                const int h = i * 128 + tid;
                if (h < NHID) nvv[i] = __ldg(crn + h);
            }
        }
        __syncthreads();

        if (warp == 0) {
            const uint32_t mw = masks[par][lane];
            const int cnt = __popc(mw);
            int inc = cnt;
#pragma unroll
            for (int d = 1; d < 32; d <<= 1) {
                const int v = __shfl_up_sync(0xffffffffu, inc, d);
                if (lane >= d) inc += v;
            }
            const int excl = inc - cnt;
            const int tot = __shfl_sync(0xffffffffu, inc, 31);
            const int p1  = __shfl_sync(0xffffffffu, excl, 10);  // h = 320
            const int p2  = __shfl_sync(0xffffffffu, excl, 20);  // h = 640
            {
                uint32_t m2w = mw;
                int o = excl;
                const int base = lane * 32;
                while (m2w) {
                    const int bi = __ffs(m2w) - 1;
                    list[par][o++] = (uint16_t)(base + bi);
                    m2w &= m2w - 1;
                }
            }
            __syncwarp();

            if (lane < NOUT) {
                const float* wrow = &W2s[lane * W2P];
                const uint16_t* L = list[par];
                float acc = 0.f;
                int s0 = 0, s1 = p1;
#pragma unroll
                for (int seg = 0; seg < 3; ++seg) {
                    float pacc = 0.f;
#pragma unroll 8
                    for (int ii = s0; ii < s1; ++ii)
                        pacc = __fadd_rn(pacc, wrow[L[ii]]);
                    acc = __fadd_rn(acc, pacc);
                    s0 = s1;
                    s1 = (seg == 0) ? p2 : tot;
                }
                const float c2v = __fadd_rn(acc, b2v);
                const float m2 = __fsub_rn(__fadd_rn(__fmul_rn(0.9f, mem2), c2v), rst2);
                const float s2 = (m2 > 1.0f) ? 1.0f : 0.0f;
                mem2 = m2;
                rst2 = s2;
                const size_t idx = ((size_t)t * BB + b) * NOUT + lane;
                out[idx] = s2;
                out[(size_t)TT * BB * NOUT + idx] = m2;
            }
        }

        par ^= 1;
#pragma unroll
        for (int i = 0; i < 8; ++i) cv[i] = nvv[i];
    }
}

// ---------------------------------------------------------------------------
extern "C" void kernel_launch(void* const* d_in, const int* in_sizes, int n_in,
                              void* d_out, int out_size)
{
    const float* x  = (const float*)d_in[0];
    const float* W1 = (const float*)d_in[1];
    const float* b1 = (const float*)d_in[2];
    const float* W2 = (const float*)d_in[3];
    const float* b2 = (const float*)d_in[4];
    float* out = (float*)d_out;

    dim3 grid((NHID + BN - 1) / BN, (TT * BB) / BM);   // (8, 800)
    gemm_cur1_kernel<<<grid, 256>>>(x, W1, b1);

    lif_kernel<<<BB, 128>>>(W2, b2, out);
}